// round 1
// baseline (speedup 1.0000x reference)
#include <cuda_runtime.h>
#include <math.h>

#define T_TOK 8192
#define HDIM  1024
#define IDIM  2816
#define NEXP  8

// ---------------- scratch (device globals; no allocations allowed) ----------
__device__ int   g_cnt[NEXP];
__device__ int   g_tok[NEXP * T_TOK];
__device__ float g_wt [NEXP * T_TOK];
// h = silu(gate)*up, one row per (expert, slot). 8*8192*2816*4B = 736 MB.
__device__ float g_h[(size_t)NEXP * T_TOK * IDIM];

// ---------------- kernel 0: zero per-expert counters ------------------------
__global__ void zero_cnt_kernel() {
    if (threadIdx.x < NEXP) g_cnt[threadIdx.x] = 0;
}

// ---------------- kernel 1: router (top-2 of softmax, renormalized) ---------
// softmax -> top2 -> renorm == softmax over the two top logits (denominator cancels)
__global__ void router_kernel(const float* __restrict__ logits) {
    int t = blockIdx.x * blockDim.x + threadIdx.x;
    if (t >= T_TOK) return;
    float l[NEXP];
#pragma unroll
    for (int e = 0; e < NEXP; e++) l[e] = logits[t * NEXP + e];
    int a = 0;
#pragma unroll
    for (int e = 1; e < NEXP; e++) if (l[e] > l[a]) a = e;
    int b = (a == 0) ? 1 : 0;
#pragma unroll
    for (int e = 0; e < NEXP; e++) if (e != a && l[e] > l[b]) b = e;
    float d  = expf(l[b] - l[a]);          // <= 1
    float wa = 1.0f / (1.0f + d);
    float wb = d / (1.0f + d);
    int pa = atomicAdd(&g_cnt[a], 1);
    g_tok[a * T_TOK + pa] = t;  g_wt[a * T_TOK + pa] = wa;
    int pb = atomicAdd(&g_cnt[b], 1);
    g_tok[b * T_TOK + pb] = t;  g_wt[b * T_TOK + pb] = wb;
}

// ---------------- kernel 2: grouped GEMM1 + SiLU-gate ------------------------
// h[slot, i] = silu(x[tok] . w1[e,i,:]) * (x[tok] . w3[e,i,:])
#define TM1 128
#define TN1 64
#define TK1 16

__global__ void __launch_bounds__(256, 2)
gemm1_kernel(const float* __restrict__ x, const float* __restrict__ w13) {
    const int e    = blockIdx.z;
    const int cnt  = g_cnt[e];
    const int row0 = blockIdx.y * TM1;
    if (row0 >= cnt) return;
    const int col0 = blockIdx.x * TN1;

    __shared__ int stok[TM1];
    __shared__ __align__(16) float As[TK1][TM1 + 4];
    __shared__ __align__(16) float Bg[TK1][TN1 + 4];
    __shared__ __align__(16) float Bu[TK1][TN1 + 4];

    const int tid = threadIdx.x;
    for (int i = tid; i < TM1; i += 256) {
        int r = row0 + i;
        stok[i] = (r < cnt) ? g_tok[e * T_TOK + r] : 0;
    }
    __syncthreads();

    const float* wg = w13 + (size_t)e * 2 * IDIM * HDIM + (size_t)col0 * HDIM;
    const float* wu = wg + (size_t)IDIM * HDIM;

    float accg[8][4], accu[8][4];
#pragma unroll
    for (int i = 0; i < 8; i++)
#pragma unroll
        for (int j = 0; j < 4; j++) { accg[i][j] = 0.f; accu[i][j] = 0.f; }

    const int tx = tid & 15, ty = tid >> 4;

    for (int k0 = 0; k0 < HDIM; k0 += TK1) {
        // A tile: 128x16 = 512 float4, 2 per thread (gathered token rows)
#pragma unroll
        for (int it = 0; it < 2; it++) {
            int v  = tid + it * 256;
            int m  = v >> 2;
            int kq = (v & 3) * 4;
            float4 f = *(const float4*)(x + (size_t)stok[m] * HDIM + k0 + kq);
            As[kq + 0][m] = f.x; As[kq + 1][m] = f.y;
            As[kq + 2][m] = f.z; As[kq + 3][m] = f.w;
        }
        // B tiles (gate + up): 64x16 each = 256 float4 each, 1 per thread
        {
            int v  = tid;
            int n  = v >> 2;
            int kq = (v & 3) * 4;
            float4 f = *(const float4*)(wg + (size_t)n * HDIM + k0 + kq);
            Bg[kq + 0][n] = f.x; Bg[kq + 1][n] = f.y;
            Bg[kq + 2][n] = f.z; Bg[kq + 3][n] = f.w;
            float4 u = *(const float4*)(wu + (size_t)n * HDIM + k0 + kq);
            Bu[kq + 0][n] = u.x; Bu[kq + 1][n] = u.y;
            Bu[kq + 2][n] = u.z; Bu[kq + 3][n] = u.w;
        }
        __syncthreads();
#pragma unroll
        for (int kk = 0; kk < TK1; kk++) {
            float4 a0 = *(const float4*)&As[kk][ty * 8];
            float4 a1 = *(const float4*)&As[kk][ty * 8 + 4];
            float4 bg = *(const float4*)&Bg[kk][tx * 4];
            float4 bu = *(const float4*)&Bu[kk][tx * 4];
            float a[8]  = {a0.x, a0.y, a0.z, a0.w, a1.x, a1.y, a1.z, a1.w};
            float bgv[4] = {bg.x, bg.y, bg.z, bg.w};
            float buv[4] = {bu.x, bu.y, bu.z, bu.w};
#pragma unroll
            for (int i = 0; i < 8; i++)
#pragma unroll
                for (int j = 0; j < 4; j++) {
                    accg[i][j] += a[i] * bgv[j];
                    accu[i][j] += a[i] * buv[j];
                }
        }
        __syncthreads();
    }

#pragma unroll
    for (int i = 0; i < 8; i++) {
        int r = row0 + ty * 8 + i;
        if (r < cnt) {
            float* hp = g_h + ((size_t)e * T_TOK + r) * IDIM + col0 + tx * 4;
#pragma unroll
            for (int j = 0; j < 4; j++) {
                float g = accg[i][j];
                float s = g / (1.0f + expf(-g));   // silu
                hp[j]   = s * accu[i][j];
            }
        }
    }
}

// ---------------- kernel 3: grouped GEMM2 + weighted combine ----------------
// out[tok, hh] += w * (h[slot,:] . w2[e,hh,:])
#define TM2 128
#define TN2 64
#define TK2 16

__global__ void __launch_bounds__(256, 2)
gemm2_kernel(const float* __restrict__ w2, float* __restrict__ out) {
    const int e    = blockIdx.z;
    const int cnt  = g_cnt[e];
    const int row0 = blockIdx.y * TM2;
    if (row0 >= cnt) return;
    const int col0 = blockIdx.x * TN2;

    __shared__ __align__(16) float As[TK2][TM2 + 4];
    __shared__ __align__(16) float Bs[TK2][TN2 + 4];

    const int tid = threadIdx.x;
    const int tx = tid & 15, ty = tid >> 4;

    const float* hbase = g_h + ((size_t)e * T_TOK + row0) * IDIM;
    const float* wb    = w2 + (size_t)e * HDIM * IDIM + (size_t)col0 * IDIM;

    float acc[8][4];
#pragma unroll
    for (int i = 0; i < 8; i++)
#pragma unroll
        for (int j = 0; j < 4; j++) acc[i][j] = 0.f;

    for (int k0 = 0; k0 < IDIM; k0 += TK2) {
#pragma unroll
        for (int it = 0; it < 2; it++) {
            int v  = tid + it * 256;
            int m  = v >> 2;
            int kq = (v & 3) * 4;
            float4 f = *(const float4*)(hbase + (size_t)m * IDIM + k0 + kq);
            As[kq + 0][m] = f.x; As[kq + 1][m] = f.y;
            As[kq + 2][m] = f.z; As[kq + 3][m] = f.w;
        }
        {
            int v  = tid;
            int n  = v >> 2;
            int kq = (v & 3) * 4;
            float4 f = *(const float4*)(wb + (size_t)n * IDIM + k0 + kq);
            Bs[kq + 0][n] = f.x; Bs[kq + 1][n] = f.y;
            Bs[kq + 2][n] = f.z; Bs[kq + 3][n] = f.w;
        }
        __syncthreads();
#pragma unroll
        for (int kk = 0; kk < TK2; kk++) {
            float4 a0 = *(const float4*)&As[kk][ty * 8];
            float4 a1 = *(const float4*)&As[kk][ty * 8 + 4];
            float4 b  = *(const float4*)&Bs[kk][tx * 4];
            float a[8]  = {a0.x, a0.y, a0.z, a0.w, a1.x, a1.y, a1.z, a1.w};
            float bv[4] = {b.x, b.y, b.z, b.w};
#pragma unroll
            for (int i = 0; i < 8; i++)
#pragma unroll
                for (int j = 0; j < 4; j++) acc[i][j] += a[i] * bv[j];
        }
        __syncthreads();
    }

#pragma unroll
    for (int i = 0; i < 8; i++) {
        int r = row0 + ty * 8 + i;
        if (r < cnt) {
            int   t = g_tok[e * T_TOK + r];
            float w = g_wt [e * T_TOK + r];
            float* op = out + (size_t)t * HDIM + col0 + tx * 4;
#pragma unroll
            for (int j = 0; j < 4; j++) atomicAdd(&op[j], w * acc[i][j]);
        }
    }
}

// ---------------- launch --------------------------------------------------
extern "C" void kernel_launch(void* const* d_in, const int* in_sizes, int n_in,
                              void* d_out, int out_size) {
    const float* x      = (const float*)d_in[0];
    const float* logits = (const float*)d_in[1];
    const float* w13    = (const float*)d_in[2];
    const float* w2     = (const float*)d_in[3];
    float* out = (float*)d_out;
    (void)in_sizes; (void)n_in; (void)out_size;

    zero_cnt_kernel<<<1, 32>>>();
    router_kernel<<<T_TOK / 256, 256>>>(logits);
    cudaMemsetAsync(d_out, 0, (size_t)T_TOK * HDIM * sizeof(float));

    dim3 g1(IDIM / TN1, T_TOK / TM1, NEXP);   // (44, 64, 8)
    gemm1_kernel<<<g1, 256>>>(x, w13);

    dim3 g2(HDIM / TN2, T_TOK / TM2, NEXP);   // (16, 64, 8)
    gemm2_kernel<<<g2, 256>>>(w2, out);
}

// round 2
// speedup vs baseline: 1.0023x; 1.0023x over previous
#include <cuda_runtime.h>
#include <math.h>

#define T_TOK 8192
#define HDIM  1024
#define IDIM  2816
#define NEXP  8

// ---------------- scratch (device globals; no allocations allowed) ----------
__device__ int   g_cnt[NEXP];
__device__ int   g_tok[NEXP * T_TOK];
__device__ float g_wt [NEXP * T_TOK];
// h = silu(gate)*up, one row per (expert, slot). 8*8192*2816*4B = 736 MB.
__device__ float g_h[(size_t)NEXP * T_TOK * IDIM];

// ---------------- kernel 0: zero per-expert counters ------------------------
__global__ void zero_cnt_kernel() {
    if (threadIdx.x < NEXP) g_cnt[threadIdx.x] = 0;
}

// ---------------- kernel 1: router (top-2 of softmax, renormalized) ---------
// softmax -> top2 -> renorm == softmax over the two top logits (denominator cancels)
__global__ void router_kernel(const float* __restrict__ logits) {
    int t = blockIdx.x * blockDim.x + threadIdx.x;
    if (t >= T_TOK) return;
    float l[NEXP];
#pragma unroll
    for (int e = 0; e < NEXP; e++) l[e] = logits[t * NEXP + e];
    int a = 0;
#pragma unroll
    for (int e = 1; e < NEXP; e++) if (l[e] > l[a]) a = e;
    int b = (a == 0) ? 1 : 0;
#pragma unroll
    for (int e = 0; e < NEXP; e++) if (e != a && l[e] > l[b]) b = e;
    float d  = expf(l[b] - l[a]);          // <= 1
    float wa = 1.0f / (1.0f + d);
    float wb = d / (1.0f + d);
    int pa = atomicAdd(&g_cnt[a], 1);
    g_tok[a * T_TOK + pa] = t;  g_wt[a * T_TOK + pa] = wa;
    int pb = atomicAdd(&g_cnt[b], 1);
    g_tok[b * T_TOK + pb] = t;  g_wt[b * T_TOK + pb] = wb;
}

// ---------------- kernel 2: grouped GEMM1 + SiLU-gate ------------------------
// h[slot, i] = silu(x[tok] . w1[e,i,:]) * (x[tok] . w3[e,i,:])
#define TM1 128
#define TN1 64
#define TK1 16

__global__ void __launch_bounds__(256, 2)
gemm1_kernel(const float* __restrict__ x, const float* __restrict__ w13) {
    const int e    = blockIdx.z;
    const int cnt  = g_cnt[e];
    const int row0 = blockIdx.y * TM1;
    if (row0 >= cnt) return;
    const int col0 = blockIdx.x * TN1;

    __shared__ int stok[TM1];
    __shared__ __align__(16) float As[TK1][TM1 + 4];
    __shared__ __align__(16) float Bg[TK1][TN1 + 4];
    __shared__ __align__(16) float Bu[TK1][TN1 + 4];

    const int tid = threadIdx.x;
    for (int i = tid; i < TM1; i += 256) {
        int r = row0 + i;
        stok[i] = (r < cnt) ? g_tok[e * T_TOK + r] : 0;
    }
    __syncthreads();

    const float* wg = w13 + (size_t)e * 2 * IDIM * HDIM + (size_t)col0 * HDIM;
    const float* wu = wg + (size_t)IDIM * HDIM;

    float accg[8][4], accu[8][4];
#pragma unroll
    for (int i = 0; i < 8; i++)
#pragma unroll
        for (int j = 0; j < 4; j++) { accg[i][j] = 0.f; accu[i][j] = 0.f; }

    const int tx = tid & 15, ty = tid >> 4;

    for (int k0 = 0; k0 < HDIM; k0 += TK1) {
        // A tile: 128x16 = 512 float4, 2 per thread (gathered token rows)
#pragma unroll
        for (int it = 0; it < 2; it++) {
            int v  = tid + it * 256;
            int m  = v >> 2;
            int kq = (v & 3) * 4;
            float4 f = *(const float4*)(x + (size_t)stok[m] * HDIM + k0 + kq);
            As[kq + 0][m] = f.x; As[kq + 1][m] = f.y;
            As[kq + 2][m] = f.z; As[kq + 3][m] = f.w;
        }
        // B tiles (gate + up): 64x16 each = 256 float4 each, 1 per thread
        {
            int v  = tid;
            int n  = v >> 2;
            int kq = (v & 3) * 4;
            float4 f = *(const float4*)(wg + (size_t)n * HDIM + k0 + kq);
            Bg[kq + 0][n] = f.x; Bg[kq + 1][n] = f.y;
            Bg[kq + 2][n] = f.z; Bg[kq + 3][n] = f.w;
            float4 u = *(const float4*)(wu + (size_t)n * HDIM + k0 + kq);
            Bu[kq + 0][n] = u.x; Bu[kq + 1][n] = u.y;
            Bu[kq + 2][n] = u.z; Bu[kq + 3][n] = u.w;
        }
        __syncthreads();
#pragma unroll
        for (int kk = 0; kk < TK1; kk++) {
            float4 a0 = *(const float4*)&As[kk][ty * 8];
            float4 a1 = *(const float4*)&As[kk][ty * 8 + 4];
            float4 bg = *(const float4*)&Bg[kk][tx * 4];
            float4 bu = *(const float4*)&Bu[kk][tx * 4];
            float a[8]  = {a0.x, a0.y, a0.z, a0.w, a1.x, a1.y, a1.z, a1.w};
            float bgv[4] = {bg.x, bg.y, bg.z, bg.w};
            float buv[4] = {bu.x, bu.y, bu.z, bu.w};
#pragma unroll
            for (int i = 0; i < 8; i++)
#pragma unroll
                for (int j = 0; j < 4; j++) {
                    accg[i][j] += a[i] * bgv[j];
                    accu[i][j] += a[i] * buv[j];
                }
        }
        __syncthreads();
    }

#pragma unroll
    for (int i = 0; i < 8; i++) {
        int r = row0 + ty * 8 + i;
        if (r < cnt) {
            float* hp = g_h + ((size_t)e * T_TOK + r) * IDIM + col0 + tx * 4;
#pragma unroll
            for (int j = 0; j < 4; j++) {
                float g = accg[i][j];
                float s = g / (1.0f + expf(-g));   // silu
                hp[j]   = s * accu[i][j];
            }
        }
    }
}

// ---------------- kernel 3: grouped GEMM2 + weighted combine ----------------
// out[tok, hh] += w * (h[slot,:] . w2[e,hh,:])
#define TM2 128
#define TN2 64
#define TK2 16

__global__ void __launch_bounds__(256, 2)
gemm2_kernel(const float* __restrict__ w2, float* __restrict__ out) {
    const int e    = blockIdx.z;
    const int cnt  = g_cnt[e];
    const int row0 = blockIdx.y * TM2;
    if (row0 >= cnt) return;
    const int col0 = blockIdx.x * TN2;

    __shared__ __align__(16) float As[TK2][TM2 + 4];
    __shared__ __align__(16) float Bs[TK2][TN2 + 4];

    const int tid = threadIdx.x;
    const int tx = tid & 15, ty = tid >> 4;

    const float* hbase = g_h + ((size_t)e * T_TOK + row0) * IDIM;
    const float* wb    = w2 + (size_t)e * HDIM * IDIM + (size_t)col0 * IDIM;

    float acc[8][4];
#pragma unroll
    for (int i = 0; i < 8; i++)
#pragma unroll
        for (int j = 0; j < 4; j++) acc[i][j] = 0.f;

    for (int k0 = 0; k0 < IDIM; k0 += TK2) {
#pragma unroll
        for (int it = 0; it < 2; it++) {
            int v  = tid + it * 256;
            int m  = v >> 2;
            int kq = (v & 3) * 4;
            float4 f = *(const float4*)(hbase + (size_t)m * IDIM + k0 + kq);
            As[kq + 0][m] = f.x; As[kq + 1][m] = f.y;
            As[kq + 2][m] = f.z; As[kq + 3][m] = f.w;
        }
        {
            int v  = tid;
            int n  = v >> 2;
            int kq = (v & 3) * 4;
            float4 f = *(const float4*)(wb + (size_t)n * IDIM + k0 + kq);
            Bs[kq + 0][n] = f.x; Bs[kq + 1][n] = f.y;
            Bs[kq + 2][n] = f.z; Bs[kq + 3][n] = f.w;
        }
        __syncthreads();
#pragma unroll
        for (int kk = 0; kk < TK2; kk++) {
            float4 a0 = *(const float4*)&As[kk][ty * 8];
            float4 a1 = *(const float4*)&As[kk][ty * 8 + 4];
            float4 b  = *(const float4*)&Bs[kk][tx * 4];
            float a[8]  = {a0.x, a0.y, a0.z, a0.w, a1.x, a1.y, a1.z, a1.w};
            float bv[4] = {b.x, b.y, b.z, b.w};
#pragma unroll
            for (int i = 0; i < 8; i++)
#pragma unroll
                for (int j = 0; j < 4; j++) acc[i][j] += a[i] * bv[j];
        }
        __syncthreads();
    }

#pragma unroll
    for (int i = 0; i < 8; i++) {
        int r = row0 + ty * 8 + i;
        if (r < cnt) {
            int   t = g_tok[e * T_TOK + r];
            float w = g_wt [e * T_TOK + r];
            float* op = out + (size_t)t * HDIM + col0 + tx * 4;
#pragma unroll
            for (int j = 0; j < 4; j++) atomicAdd(&op[j], w * acc[i][j]);
        }
    }
}

// ---------------- launch --------------------------------------------------
extern "C" void kernel_launch(void* const* d_in, const int* in_sizes, int n_in,
                              void* d_out, int out_size) {
    const float* x      = (const float*)d_in[0];
    const float* logits = (const float*)d_in[1];
    const float* w13    = (const float*)d_in[2];
    const float* w2     = (const float*)d_in[3];
    float* out = (float*)d_out;
    (void)in_sizes; (void)n_in; (void)out_size;

    zero_cnt_kernel<<<1, 32>>>();
    router_kernel<<<T_TOK / 256, 256>>>(logits);
    cudaMemsetAsync(d_out, 0, (size_t)T_TOK * HDIM * sizeof(float));

    dim3 g1(IDIM / TN1, T_TOK / TM1, NEXP);   // (44, 64, 8)
    gemm1_kernel<<<g1, 256>>>(x, w13);

    dim3 g2(HDIM / TN2, T_TOK / TM2, NEXP);   // (16, 64, 8)
    gemm2_kernel<<<g2, 256>>>(w2, out);
}